// round 1
// baseline (speedup 1.0000x reference)
#include <cuda_runtime.h>
#include <cstdint>

// x: (2, 3, 256, 256, 256) float32
// out: (2, 256, 256, 256) float32
//
// out[b,z,y,i] = 0.5 * ( u[b,z,y,(i+1)&255] - u[b,z,y,(i-1)&255]
//                      + v[b,z,(y+1)&255,i] - v[b,z,(y-1)&255,i]
//                      + w[b,(z+1)&255,(y+1)&255,i] - w[b,(z-1)&255,(y-1)&255,i] )
//
// One thread per float4 of output: 2*256*256*64 = 8,388,608 threads.

#define DIM 256
#define DIMM 255            // mask
#define Q 64                // float4s per row
#define PLANE (DIM * DIM)   // floats per z-slice row-block
#define VOL (DIM * DIM * DIM)

__global__ __launch_bounds__(256) void calc_divergence_kernel(
    const float* __restrict__ x, float* __restrict__ out)
{
    // flat float4 index
    const uint32_t idx = blockIdx.x * blockDim.x + threadIdx.x;
    // decompose: [b:1][z:8][y:8][xq:6]
    const uint32_t xq = idx & (Q - 1);
    const uint32_t y  = (idx >> 6) & DIMM;
    const uint32_t z  = (idx >> 14) & DIMM;
    const uint32_t b  = idx >> 22;

    const uint32_t i0 = xq << 2;   // first float column handled by this thread

    const float* u = x + (size_t)(b * 3 + 0) * VOL;
    const float* v = x + (size_t)(b * 3 + 1) * VOL;
    const float* w = x + (size_t)(b * 3 + 2) * VOL;

    const uint32_t yp = (y + 1) & DIMM;
    const uint32_t ym = (y - 1) & DIMM;
    const uint32_t zp = (z + 1) & DIMM;
    const uint32_t zm = (z - 1) & DIMM;

    // ---- u: x-direction central difference (periodic) ----
    const float* urow = u + ((size_t)z * DIM + y) * DIM;
    const float4 uc = *reinterpret_cast<const float4*>(urow + i0);
    const float  ul = urow[(i0 - 1) & DIMM];   // u[i0-1]
    const float  ur = urow[(i0 + 4) & DIMM];   // u[i0+4]

    float4 du;
    du.x = uc.y - ul;
    du.y = uc.z - uc.x;
    du.z = uc.w - uc.y;
    du.w = ur   - uc.z;

    // ---- v: y-direction central difference ----
    const float4 vp = *reinterpret_cast<const float4*>(v + ((size_t)z * DIM + yp) * DIM + i0);
    const float4 vm = *reinterpret_cast<const float4*>(v + ((size_t)z * DIM + ym) * DIM + i0);

    // ---- w: diagonal (z,y) central difference ----
    const float4 wp = *reinterpret_cast<const float4*>(w + ((size_t)zp * DIM + yp) * DIM + i0);
    const float4 wm = *reinterpret_cast<const float4*>(w + ((size_t)zm * DIM + ym) * DIM + i0);

    float4 r;
    r.x = 0.5f * (du.x + (vp.x - vm.x) + (wp.x - wm.x));
    r.y = 0.5f * (du.y + (vp.y - vm.y) + (wp.y - wm.y));
    r.z = 0.5f * (du.z + (vp.z - vm.z) + (wp.z - wm.z));
    r.w = 0.5f * (du.w + (vp.w - vm.w) + (wp.w - wm.w));

    *reinterpret_cast<float4*>(out + ((size_t)(b * DIM + z) * DIM + y) * DIM + i0) = r;
}

extern "C" void kernel_launch(void* const* d_in, const int* in_sizes, int n_in,
                              void* d_out, int out_size)
{
    const float* x = (const float*)d_in[0];
    float* out = (float*)d_out;

    const uint32_t total_f4 = 2u * DIM * DIM * Q;   // 8,388,608
    const uint32_t threads = 256;
    const uint32_t blocks = total_f4 / threads;     // 32,768

    calc_divergence_kernel<<<blocks, threads>>>(x, out);
}